// round 10
// baseline (speedup 1.0000x reference)
#include <cuda_runtime.h>
#include <cstdint>

// Problem constants
#define BB 8
#define NN 8192
#define SS 1024
#define KK 32
static constexpr int M_ROWS = BB * SS * KK;   // 262144 grouped rows
static constexpr float EPSf = 1e-5f;

// -------- device scratch (static allocations; no cudaMalloc allowed) --------
__device__ float  g_h0[(size_t)M_ROWS * 64];   // layer0 output (pre-BN)   64 MB
__device__ float  g_h1[(size_t)M_ROWS * 64];   // layer1 output (pre-BN)   64 MB
__device__ float  g_h2[(size_t)M_ROWS * 128];  // layer2 output (pre-BN)  128 MB
__device__ int    g_gidx[M_ROWS];              // ball-query indices
__device__ double g_sum[256];                  // per-channel sums  (0:64 L0, 64:128 L1, 128:256 L2)
__device__ double g_sq[256];                   // per-channel sum of squares
__device__ float  g_a[256];                    // BN scale  a = g * rsqrt(var+eps)
__device__ float  g_cs[256];                   // BN shift  c = be - m * a

// ---------------------------------------------------------------------------
__global__ void k_init() {
    int i = threadIdx.x;
    if (i < 256) { g_sum[i] = 0.0; g_sq[i] = 0.0; }
}

// -------------------------- FPS: one CTA per batch --------------------------
// Reproduces jnp semantics: cents[0]=0; then 1023 rounds of
//   dist = min(dist, ||x - xyz[far]||^2);  far = argmax(dist) (first max wins)
// Distances use non-FMA rn ops in fold order ((dx^2+dy^2)+dz^2).
__global__ void __launch_bounds__(1024, 1)
k_fps(const float* __restrict__ xyz, float* __restrict__ out) {
    int b = blockIdx.x;
    const float* X = xyz + (size_t)b * NN * 3;
    float px[8], py[8], pz[8], dist[8];
    int base = threadIdx.x * 8;
#pragma unroll
    for (int j = 0; j < 8; j++) {
        px[j] = X[(base + j) * 3 + 0];
        py[j] = X[(base + j) * 3 + 1];
        pz[j] = X[(base + j) * 3 + 2];
        dist[j] = 1e10f;
    }
    __shared__ float    s_c[3];
    __shared__ unsigned s_bits[32];
    __shared__ int      s_idx[32];
    int lane = threadIdx.x & 31, warp = threadIdx.x >> 5;

    if (threadIdx.x == 0) {
        float cx = X[0], cy = X[1], cz = X[2];
        s_c[0] = cx; s_c[1] = cy; s_c[2] = cz;
        float* o = out + (size_t)b * SS * 3;
        o[0] = cx; o[1] = cy; o[2] = cz;
    }
    __syncthreads();

    for (int s = 1; s < SS; s++) {
        float cx = s_c[0], cy = s_c[1], cz = s_c[2];
        float best = -1.0f; int bidx = base;
#pragma unroll
        for (int j = 0; j < 8; j++) {
            float dx = __fsub_rn(px[j], cx);
            float dy = __fsub_rn(py[j], cy);
            float dz = __fsub_rn(pz[j], cz);
            float d  = __fadd_rn(__fadd_rn(__fmul_rn(dx, dx), __fmul_rn(dy, dy)),
                                 __fmul_rn(dz, dz));
            float nd = fminf(dist[j], d);
            dist[j] = nd;
            if (nd > best) { best = nd; bidx = base + j; }
        }
        // dist >= 0 so float ordering == uint-bit ordering
        unsigned bb   = __float_as_uint(best);
        unsigned m    = __reduce_max_sync(0xffffffffu, bb);
        unsigned cand = (bb == m) ? (unsigned)bidx : 0xffffffffu;
        unsigned mi   = __reduce_min_sync(0xffffffffu, cand);
        if (lane == 0) { s_bits[warp] = m; s_idx[warp] = (int)mi; }
        __syncthreads();
        if (warp == 0) {
            unsigned wb = s_bits[lane];
            unsigned wi = (unsigned)s_idx[lane];
            unsigned m2 = __reduce_max_sync(0xffffffffu, wb);
            unsigned c2 = (wb == m2) ? wi : 0xffffffffu;
            unsigned i2 = __reduce_min_sync(0xffffffffu, c2);
            if (lane == 0) {
                float cx2 = X[i2 * 3], cy2 = X[i2 * 3 + 1], cz2 = X[i2 * 3 + 2];
                s_c[0] = cx2; s_c[1] = cy2; s_c[2] = cz2;
                float* o = out + ((size_t)b * SS + s) * 3;
                o[0] = cx2; o[1] = cy2; o[2] = cz2;
            }
        }
        __syncthreads();
    }
}

// ------------------------ Ball query: one warp per query --------------------
// Replicates the expanded distance  (s2 + n2) - 2*dot  with non-FMA rn ops;
// collects the first K passing indices in ascending order, pads with first.
__global__ void __launch_bounds__(256)
k_ball(const float* __restrict__ xyz, const float* __restrict__ newxyz) {
    const float R2 = (float)(0.2 * 0.2);
    int warp = threadIdx.x >> 5, lane = threadIdx.x & 31;
    int q = blockIdx.x * 8 + warp;           // q in [0, B*S)
    int b = q >> 10;                          // S = 1024
    const float* X = xyz + (size_t)b * NN * 3;
    float nx = newxyz[q * 3], ny = newxyz[q * 3 + 1], nz = newxyz[q * 3 + 2];
    float s2 = __fadd_rn(__fadd_rn(__fmul_rn(nx, nx), __fmul_rn(ny, ny)),
                         __fmul_rn(nz, nz));
    __shared__ int s_list[8][KK];
    int found = 0;
    for (int basep = 0; basep < NN; basep += 32) {
        int n = basep + lane;
        float x = X[n * 3], y = X[n * 3 + 1], z = X[n * 3 + 2];
        float n2  = __fadd_rn(__fadd_rn(__fmul_rn(x, x), __fmul_rn(y, y)),
                              __fmul_rn(z, z));
        float dot = __fadd_rn(__fadd_rn(__fmul_rn(nx, x), __fmul_rn(ny, y)),
                              __fmul_rn(nz, z));
        float sq  = __fsub_rn(__fadd_rn(s2, n2), __fmul_rn(2.0f, dot));
        bool pass = !(sq > R2);
        unsigned msk = __ballot_sync(0xffffffffu, pass);
        int pos = found + __popc(msk & ((1u << lane) - 1u));
        if (pass && pos < KK) s_list[warp][pos] = n;
        found += __popc(msk);
        if (found >= KK) break;              // warp-uniform
    }
    __syncwarp();
    int cnt = found < KK ? found : KK;       // >= 1 (centroid itself passes exactly)
    int first = s_list[warp][0];
    int v = (lane < cnt) ? s_list[warp][lane] : first;
    g_gidx[q * KK + lane] = v;
}

// ------------------- Layer0: gather + 9->64 matmul + stats ------------------
__global__ void __launch_bounds__(256)
k_layer0(const float* __restrict__ points, const float* __restrict__ xyz,
         const float* __restrict__ newxyz, const float* __restrict__ W0,
         const float* __restrict__ b0) {
    __shared__ __align__(16) float s_W[9 * 64];
    __shared__ float s_b[64];
    __shared__ float s_feat[4][12];
    __shared__ float s_red[4][64];
    int tid = threadIdx.x;
    for (int i = tid; i < 576; i += 256) s_W[i] = W0[i];
    if (tid < 64) s_b[tid] = b0[tid];
    int c = tid & 63, y = tid >> 6;
    float lsum = 0.f, lsq = 0.f;
    int row0 = blockIdx.x * 128;             // 32 tiles * 4 rows
    __syncthreads();
    for (int t = 0; t < 32; t++) {
        int row = row0 + t * 4 + y;
        if (c < 9) {
            int i = g_gidx[row];
            int b = row >> 15;               // S*K = 32768
            float f;
            if (c < 6) {
                f = points[((size_t)b * NN + i) * 6 + c];
            } else {
                int s = (row >> 5) & 1023;
                f = xyz[((size_t)b * NN + i) * 3 + (c - 6)]
                  - newxyz[((size_t)((b << 10) | s)) * 3 + (c - 6)];
            }
            s_feat[y][c] = f;
        }
        __syncthreads();
        float acc = s_b[c];
#pragma unroll
        for (int j = 0; j < 9; j++) acc = fmaf(s_feat[y][j], s_W[j * 64 + c], acc);
        g_h0[(size_t)row * 64 + c] = acc;
        lsum += acc; lsq = fmaf(acc, acc, lsq);
        __syncthreads();
    }
    s_red[y][c] = lsum; __syncthreads();
    if (tid < 64) {
        float t0 = s_red[0][tid] + s_red[1][tid] + s_red[2][tid] + s_red[3][tid];
        atomicAdd(&g_sum[tid], (double)t0);
    }
    __syncthreads();
    s_red[y][c] = lsq; __syncthreads();
    if (tid < 64) {
        float t0 = s_red[0][tid] + s_red[1][tid] + s_red[2][tid] + s_red[3][tid];
        atomicAdd(&g_sq[tid], (double)t0);
    }
}

// ------------------------- BN stats finalize (tiny) --------------------------
__global__ void k_finalize(const float* __restrict__ g, const float* __restrict__ be,
                           int off, int C) {
    int c = threadIdx.x;
    if (c < C) {
        const double invM = 1.0 / (double)M_ROWS;
        double m = g_sum[off + c] * invM;
        double v = g_sq[off + c] * invM - m * m;
        float rs = rsqrtf((float)v + EPSf);
        float a = g[c] * rs;
        g_a[off + c] = a;
        g_cs[off + c] = fmaf(-(float)m, a, be[c]);
    }
}

// ---------------- Layer1: bn0+relu then 64->64 matmul + stats ----------------
__global__ void __launch_bounds__(256)
k_layer1(const float* __restrict__ W1, const float* __restrict__ b1) {
    __shared__ __align__(16) float s_W[64 * 64];
    __shared__ float s_b[64], s_a[64], s_cs[64];
    __shared__ __align__(16) float s_x[16][65];
    __shared__ float s_red[16][64];
    int tid = threadIdx.x;
    for (int i = tid; i < 4096; i += 256) s_W[i] = W1[i];
    if (tid < 64) { s_b[tid] = b1[tid]; s_a[tid] = g_a[tid]; s_cs[tid] = g_cs[tid]; }
    __syncthreads();
    int r = tid >> 4, cg = tid & 15, c0 = cg * 4;
    float ls0 = 0, ls1 = 0, ls2 = 0, ls3 = 0;
    float lq0 = 0, lq1 = 0, lq2 = 0, lq3 = 0;
    for (int t = 0; t < 8; t++) {
        int row0 = (blockIdx.x * 8 + t) * 16;
#pragma unroll
        for (int e = 0; e < 4; e++) {
            int lin = e * 256 + tid; int rr = lin >> 6, cc = lin & 63;
            float v = g_h0[(size_t)(row0 + rr) * 64 + cc];
            s_x[rr][cc] = fmaxf(fmaf(v, s_a[cc], s_cs[cc]), 0.f);
        }
        __syncthreads();
        float a0 = s_b[c0], a1 = s_b[c0 + 1], a2 = s_b[c0 + 2], a3 = s_b[c0 + 3];
#pragma unroll
        for (int j = 0; j < 64; j++) {
            float xv = s_x[r][j];
            float4 w = *reinterpret_cast<const float4*>(&s_W[j * 64 + c0]);
            a0 = fmaf(xv, w.x, a0); a1 = fmaf(xv, w.y, a1);
            a2 = fmaf(xv, w.z, a2); a3 = fmaf(xv, w.w, a3);
        }
        float4 o; o.x = a0; o.y = a1; o.z = a2; o.w = a3;
        *reinterpret_cast<float4*>(&g_h1[(size_t)(row0 + r) * 64 + c0]) = o;
        ls0 += a0; ls1 += a1; ls2 += a2; ls3 += a3;
        lq0 = fmaf(a0, a0, lq0); lq1 = fmaf(a1, a1, lq1);
        lq2 = fmaf(a2, a2, lq2); lq3 = fmaf(a3, a3, lq3);
        __syncthreads();
    }
    s_red[r][c0] = ls0; s_red[r][c0 + 1] = ls1; s_red[r][c0 + 2] = ls2; s_red[r][c0 + 3] = ls3;
    __syncthreads();
    if (tid < 64) {
        float t0 = 0.f;
#pragma unroll
        for (int rr = 0; rr < 16; rr++) t0 += s_red[rr][tid];
        atomicAdd(&g_sum[64 + tid], (double)t0);
    }
    __syncthreads();
    s_red[r][c0] = lq0; s_red[r][c0 + 1] = lq1; s_red[r][c0 + 2] = lq2; s_red[r][c0 + 3] = lq3;
    __syncthreads();
    if (tid < 64) {
        float t0 = 0.f;
#pragma unroll
        for (int rr = 0; rr < 16; rr++) t0 += s_red[rr][tid];
        atomicAdd(&g_sq[64 + tid], (double)t0);
    }
}

// ---------------- Layer2: bn1+relu then 64->128 matmul + stats ---------------
__global__ void __launch_bounds__(256)
k_layer2(const float* __restrict__ W2, const float* __restrict__ b2) {
    __shared__ __align__(16) float s_W[64 * 128];
    __shared__ float s_b[128], s_a[64], s_cs[64];
    __shared__ __align__(16) float s_x[8][65];
    __shared__ float s_red[8][128];
    int tid = threadIdx.x;
    for (int i = tid; i < 8192; i += 256) s_W[i] = W2[i];
    if (tid < 128) s_b[tid] = b2[tid];
    if (tid < 64) { s_a[tid] = g_a[64 + tid]; s_cs[tid] = g_cs[64 + tid]; }
    __syncthreads();
    int r = tid >> 5, cg = tid & 31, c0 = cg * 4;
    float ls0 = 0, ls1 = 0, ls2 = 0, ls3 = 0;
    float lq0 = 0, lq1 = 0, lq2 = 0, lq3 = 0;
    for (int t = 0; t < 16; t++) {
        int row0 = (blockIdx.x * 16 + t) * 8;
#pragma unroll
        for (int e = 0; e < 2; e++) {
            int lin = e * 256 + tid; int rr = lin >> 6, cc = lin & 63;
            float v = g_h1[(size_t)(row0 + rr) * 64 + cc];
            s_x[rr][cc] = fmaxf(fmaf(v, s_a[cc], s_cs[cc]), 0.f);
        }
        __syncthreads();
        float a0 = s_b[c0], a1 = s_b[c0 + 1], a2 = s_b[c0 + 2], a3 = s_b[c0 + 3];
#pragma unroll
        for (int j = 0; j < 64; j++) {
            float xv = s_x[r][j];
            float4 w = *reinterpret_cast<const float4*>(&s_W[j * 128 + c0]);
            a0 = fmaf(xv, w.x, a0); a1 = fmaf(xv, w.y, a1);
            a2 = fmaf(xv, w.z, a2); a3 = fmaf(xv, w.w, a3);
        }
        float4 o; o.x = a0; o.y = a1; o.z = a2; o.w = a3;
        *reinterpret_cast<float4*>(&g_h2[(size_t)(row0 + r) * 128 + c0]) = o;
        ls0 += a0; ls1 += a1; ls2 += a2; ls3 += a3;
        lq0 = fmaf(a0, a0, lq0); lq1 = fmaf(a1, a1, lq1);
        lq2 = fmaf(a2, a2, lq2); lq3 = fmaf(a3, a3, lq3);
        __syncthreads();
    }
    s_red[r][c0] = ls0; s_red[r][c0 + 1] = ls1; s_red[r][c0 + 2] = ls2; s_red[r][c0 + 3] = ls3;
    __syncthreads();
    if (tid < 128) {
        float t0 = 0.f;
#pragma unroll
        for (int rr = 0; rr < 8; rr++) t0 += s_red[rr][tid];
        atomicAdd(&g_sum[128 + tid], (double)t0);
    }
    __syncthreads();
    s_red[r][c0] = lq0; s_red[r][c0 + 1] = lq1; s_red[r][c0 + 2] = lq2; s_red[r][c0 + 3] = lq3;
    __syncthreads();
    if (tid < 128) {
        float t0 = 0.f;
#pragma unroll
        for (int rr = 0; rr < 8; rr++) t0 += s_red[rr][tid];
        atomicAdd(&g_sq[128 + tid], (double)t0);
    }
}

// ---------------- Final: bn2 + relu + max over K -> new_points ---------------
__global__ void __launch_bounds__(256)
k_maxpool(float* __restrict__ out) {
    int q = blockIdx.x * 2 + (threadIdx.x >> 7);  // query in [0, B*S)
    int c = threadIdx.x & 127;
    float a = g_a[128 + c], cs = g_cs[128 + c];
    float m = 0.f;                                 // relu outputs are >= 0
    size_t base = (size_t)q * KK * 128 + c;
#pragma unroll 8
    for (int k = 0; k < KK; k++) {
        float v = g_h2[base + (size_t)k * 128];
        m = fmaxf(m, fmaxf(fmaf(v, a, cs), 0.f));
    }
    out[(size_t)BB * SS * 3 + (size_t)q * 128 + c] = m;
}

// ---------------------------------------------------------------------------
extern "C" void kernel_launch(void* const* d_in, const int* in_sizes, int n_in,
                              void* d_out, int out_size) {
    const float* xyz    = (const float*)d_in[0];
    const float* points = (const float*)d_in[1];
    const float* W0 = (const float*)d_in[2];  const float* b0 = (const float*)d_in[3];
    const float* g0 = (const float*)d_in[4];  const float* be0 = (const float*)d_in[5];
    const float* W1 = (const float*)d_in[6];  const float* b1 = (const float*)d_in[7];
    const float* g1 = (const float*)d_in[8];  const float* be1 = (const float*)d_in[9];
    const float* W2 = (const float*)d_in[10]; const float* b2 = (const float*)d_in[11];
    const float* g2 = (const float*)d_in[12]; const float* be2 = (const float*)d_in[13];
    float* out = (float*)d_out;   // [B*S*3 new_xyz | B*S*128 new_points]

    k_init<<<1, 256>>>();
    k_fps<<<BB, 1024>>>(xyz, out);
    k_ball<<<(BB * SS) / 8, 256>>>(xyz, out);
    k_layer0<<<2048, 256>>>(points, xyz, out, W0, b0);
    k_finalize<<<1, 64>>>(g0, be0, 0, 64);
    k_layer1<<<2048, 256>>>(W1, b1);
    k_finalize<<<1, 64>>>(g1, be1, 64, 64);
    k_layer2<<<2048, 256>>>(W2, b2);
    k_finalize<<<1, 128>>>(g2, be2, 128, 128);
    k_maxpool<<<(BB * SS) / 2, 256>>>(out);
}

// round 11
// speedup vs baseline: 1.2364x; 1.2364x over previous
#include <cuda_runtime.h>
#include <cstdint>

#define BB 8
#define NN 8192
#define SS 1024
#define KK 32
static constexpr int M_ROWS = BB * SS * KK;   // 262144
static constexpr float EPSf = 1e-5f;

typedef unsigned long long ull;

// ---------------- packed f32x2 helpers (rn — bit-identical to scalar) -------
__device__ __forceinline__ ull pack2(float lo, float hi) {
    ull v; asm("mov.b64 %0, {%1, %2};" : "=l"(v) : "f"(lo), "f"(hi)); return v;
}
__device__ __forceinline__ void unpack2(ull v, float& lo, float& hi) {
    asm("mov.b64 {%0, %1}, %2;" : "=f"(lo), "=f"(hi) : "l"(v));
}
__device__ __forceinline__ ull add2(ull a, ull b) {
    ull d; asm("add.rn.f32x2 %0, %1, %2;" : "=l"(d) : "l"(a), "l"(b)); return d;
}
__device__ __forceinline__ ull mul2(ull a, ull b) {
    ull d; asm("mul.rn.f32x2 %0, %1, %2;" : "=l"(d) : "l"(a), "l"(b)); return d;
}
__device__ __forceinline__ ull fma2(ull a, ull b, ull c) {
    ull d; asm("fma.rn.f32x2 %0, %1, %2, %3;" : "=l"(d) : "l"(a), "l"(b), "l"(c)); return d;
}

// ------------------------------ device scratch ------------------------------
__device__ float  g_h0[(size_t)M_ROWS * 64];     // layer0 pre-BN   64 MB
__device__ float  g_h1[(size_t)M_ROWS * 64];     // layer1 pre-BN   64 MB
__device__ float  g_mx[(size_t)BB * SS * 128];   // per-query raw max (layer2)
__device__ float  g_mn[(size_t)BB * SS * 128];   // per-query raw min (layer2)
__device__ int    g_gidx[M_ROWS];
__device__ double g_sum[256];
__device__ double g_sq[256];
__device__ float  g_a[256];
__device__ float  g_cs[256];

__global__ void k_init() {
    int i = threadIdx.x;
    if (i < 256) { g_sum[i] = 0.0; g_sq[i] = 0.0; }
}

// -------------------------- FPS: one CTA per batch ---------------------------
// Per round: packed-f32x2 distance update (exact rn semantics), two-stage
// (value,index) reduction where ALL warps run stage-2, then the owner thread
// broadcasts the new centroid from its registers (no global gather on the
// critical path). Same op sequence / tie semantics as the passing kernel.
__global__ void __launch_bounds__(1024, 1)
k_fps(const float* __restrict__ xyz, float* __restrict__ out) {
    int b = blockIdx.x;
    const float* X = xyz + (size_t)b * NN * 3;
    int tid = threadIdx.x;
    int base = tid * 8;

    const float4* Xv = (const float4*)(X + (size_t)base * 3);
    float4 v0 = Xv[0], v1 = Xv[1], v2 = Xv[2], v3 = Xv[3], v4 = Xv[4], v5 = Xv[5];
    float px[8], py[8], pz[8];
    px[0]=v0.x; py[0]=v0.y; pz[0]=v0.z;  px[1]=v0.w; py[1]=v1.x; pz[1]=v1.y;
    px[2]=v1.z; py[2]=v1.w; pz[2]=v2.x;  px[3]=v2.y; py[3]=v2.z; pz[3]=v2.w;
    px[4]=v3.x; py[4]=v3.y; pz[4]=v3.z;  px[5]=v3.w; py[5]=v4.x; pz[5]=v4.y;
    px[6]=v4.z; py[6]=v4.w; pz[6]=v5.x;  px[7]=v5.y; py[7]=v5.z; pz[7]=v5.w;

    ull pxp0=pack2(px[0],px[1]), pxp1=pack2(px[2],px[3]), pxp2=pack2(px[4],px[5]), pxp3=pack2(px[6],px[7]);
    ull pyp0=pack2(py[0],py[1]), pyp1=pack2(py[2],py[3]), pyp2=pack2(py[4],py[5]), pyp3=pack2(py[6],py[7]);
    ull pzp0=pack2(pz[0],pz[1]), pzp1=pack2(pz[2],pz[3]), pzp2=pack2(pz[4],pz[5]), pzp3=pack2(pz[6],pz[7]);

    float dist[8];
#pragma unroll
    for (int j = 0; j < 8; j++) dist[j] = 1e10f;

    __shared__ float    s_c[3];
    __shared__ unsigned s_bits[32];
    __shared__ unsigned s_idx[32];
    int lane = tid & 31, warp = tid >> 5;

    if (tid == 0) {
        s_c[0] = px[0]; s_c[1] = py[0]; s_c[2] = pz[0];
        float* o = out + (size_t)b * SS * 3;
        o[0] = px[0]; o[1] = py[0]; o[2] = pz[0];
    }
    __syncthreads();

    for (int s = 1; s < SS; s++) {
        float cx = s_c[0], cy = s_c[1], cz = s_c[2];
        ull cxn = pack2(-cx, -cx), cyn = pack2(-cy, -cy), czn = pack2(-cz, -cz);

#define FPS_STEP(P, PX, PY, PZ)                                             \
        {                                                                    \
            ull dx = add2(PX, cxn), dy = add2(PY, cyn), dz = add2(PZ, czn);  \
            ull d  = add2(add2(mul2(dx, dx), mul2(dy, dy)), mul2(dz, dz));   \
            float da, db; unpack2(d, da, db);                                \
            dist[2*P]   = fminf(dist[2*P],   da);                            \
            dist[2*P+1] = fminf(dist[2*P+1], db);                            \
        }
        FPS_STEP(0, pxp0, pyp0, pzp0)
        FPS_STEP(1, pxp1, pyp1, pzp1)
        FPS_STEP(2, pxp2, pyp2, pzp2)
        FPS_STEP(3, pxp3, pyp3, pzp3)
#undef FPS_STEP

        float best = -1.0f; int bidx = base;
#pragma unroll
        for (int j = 0; j < 8; j++)
            if (dist[j] > best) { best = dist[j]; bidx = base + j; }

        unsigned bb   = __float_as_uint(best);                 // dist>=0: float order == uint order
        unsigned m    = __reduce_max_sync(0xffffffffu, bb);
        unsigned cand = (bb == m) ? (unsigned)bidx : 0xffffffffu;
        unsigned mi   = __reduce_min_sync(0xffffffffu, cand);
        if (lane == 0) { s_bits[warp] = m; s_idx[warp] = mi; }
        __syncthreads();

        unsigned wb = s_bits[lane], wi = s_idx[lane];
        unsigned m2 = __reduce_max_sync(0xffffffffu, wb);
        unsigned c2 = (wb == m2) ? wi : 0xffffffffu;
        unsigned i2 = __reduce_min_sync(0xffffffffu, c2);

        if ((unsigned)tid == (i2 >> 3)) {
            int j = (int)(i2 & 7u); int p = j >> 1;
            ull vx = (p == 0) ? pxp0 : (p == 1) ? pxp1 : (p == 2) ? pxp2 : pxp3;
            ull vy = (p == 0) ? pyp0 : (p == 1) ? pyp1 : (p == 2) ? pyp2 : pyp3;
            ull vz = (p == 0) ? pzp0 : (p == 1) ? pzp1 : (p == 2) ? pzp2 : pzp3;
            float xl, xh, yl, yh, zl, zh;
            unpack2(vx, xl, xh); unpack2(vy, yl, yh); unpack2(vz, zl, zh);
            float X0 = (j & 1) ? xh : xl;
            float Y0 = (j & 1) ? yh : yl;
            float Z0 = (j & 1) ? zh : zl;
            s_c[0] = X0; s_c[1] = Y0; s_c[2] = Z0;
            float* o = out + ((size_t)b * SS + s) * 3;
            o[0] = X0; o[1] = Y0; o[2] = Z0;
        }
        __syncthreads();
    }
}

// ------------------------ Ball query: one warp per query ---------------------
__global__ void __launch_bounds__(256)
k_ball(const float* __restrict__ xyz, const float* __restrict__ newxyz) {
    const float R2 = (float)(0.2 * 0.2);
    int warp = threadIdx.x >> 5, lane = threadIdx.x & 31;
    int q = blockIdx.x * 8 + warp;
    int b = q >> 10;
    const float* X = xyz + (size_t)b * NN * 3;
    float nx = newxyz[q * 3], ny = newxyz[q * 3 + 1], nz = newxyz[q * 3 + 2];
    float s2 = __fadd_rn(__fadd_rn(__fmul_rn(nx, nx), __fmul_rn(ny, ny)),
                         __fmul_rn(nz, nz));
    __shared__ int s_list[8][KK];
    int found = 0;
    for (int basep = 0; basep < NN; basep += 32) {
        int n = basep + lane;
        float x = X[n * 3], y = X[n * 3 + 1], z = X[n * 3 + 2];
        float n2  = __fadd_rn(__fadd_rn(__fmul_rn(x, x), __fmul_rn(y, y)),
                              __fmul_rn(z, z));
        float dot = __fadd_rn(__fadd_rn(__fmul_rn(nx, x), __fmul_rn(ny, y)),
                              __fmul_rn(nz, z));
        float sq  = __fsub_rn(__fadd_rn(s2, n2), __fmul_rn(2.0f, dot));
        bool pass = !(sq > R2);
        unsigned msk = __ballot_sync(0xffffffffu, pass);
        int pos = found + __popc(msk & ((1u << lane) - 1u));
        if (pass && pos < KK) s_list[warp][pos] = n;
        found += __popc(msk);
        if (found >= KK) break;
    }
    __syncwarp();
    int cnt = found < KK ? found : KK;
    int first = s_list[warp][0];
    int v = (lane < cnt) ? s_list[warp][lane] : first;
    g_gidx[q * KK + lane] = v;
}

// ---------------- Layer0: gather + 9->64 matmul (f32x2) + stats --------------
__global__ void __launch_bounds__(256)
k_layer0(const float* __restrict__ points, const float* __restrict__ xyz,
         const float* __restrict__ newxyz, const float* __restrict__ W0,
         const float* __restrict__ b0) {
    __shared__ __align__(16) float s_W[9 * 64];
    __shared__ __align__(16) float s_b[64];
    __shared__ __align__(16) ull   s_f2[16][9];
    __shared__ float s_red[16][64];
    int tid = threadIdx.x;
    for (int i = tid; i < 576; i += 256) s_W[i] = W0[i];
    if (tid < 64) s_b[tid] = b0[tid];
    __syncthreads();
    int r = tid >> 4, cg = tid & 15, c0 = cg * 4;
    ulonglong2 bp = *reinterpret_cast<const ulonglong2*>(&s_b[c0]);
    ull ls01 = 0, ls23 = 0, lq01 = 0, lq23 = 0;

    for (int t = 0; t < 8; t++) {
        int rowT = (blockIdx.x * 8 + t) * 16;
        if (tid < 144) {
            int rr = tid / 9, j = tid - rr * 9;
            int row = rowT + rr;
            int i = g_gidx[row];
            int b = row >> 15;
            float f;
            if (j < 6) {
                f = points[((size_t)b * NN + i) * 6 + j];
            } else {
                int s = (row >> 5) & 1023, cc = j - 6;
                f = xyz[((size_t)b * NN + i) * 3 + cc]
                  - newxyz[(size_t)((b << 10) | s) * 3 + cc];
            }
            s_f2[rr][j] = pack2(f, f);
        }
        __syncthreads();
        ull a01 = bp.x, a23 = bp.y;
#pragma unroll
        for (int j = 0; j < 9; j++) {
            ull f = s_f2[r][j];
            ulonglong2 w = *reinterpret_cast<const ulonglong2*>(&s_W[j * 64 + c0]);
            a01 = fma2(f, w.x, a01);
            a23 = fma2(f, w.y, a23);
        }
        ulonglong2 o; o.x = a01; o.y = a23;
        *reinterpret_cast<ulonglong2*>(&g_h0[(size_t)(rowT + r) * 64 + c0]) = o;
        ls01 = add2(ls01, a01); ls23 = add2(ls23, a23);
        lq01 = fma2(a01, a01, lq01); lq23 = fma2(a23, a23, lq23);
        __syncthreads();
    }
    float l0, l1, l2, l3;
    unpack2(ls01, l0, l1); unpack2(ls23, l2, l3);
    s_red[r][c0] = l0; s_red[r][c0+1] = l1; s_red[r][c0+2] = l2; s_red[r][c0+3] = l3;
    __syncthreads();
    if (tid < 64) {
        float t0 = 0.f;
#pragma unroll
        for (int rr = 0; rr < 16; rr++) t0 += s_red[rr][tid];
        atomicAdd(&g_sum[tid], (double)t0);
    }
    __syncthreads();
    unpack2(lq01, l0, l1); unpack2(lq23, l2, l3);
    s_red[r][c0] = l0; s_red[r][c0+1] = l1; s_red[r][c0+2] = l2; s_red[r][c0+3] = l3;
    __syncthreads();
    if (tid < 64) {
        float t0 = 0.f;
#pragma unroll
        for (int rr = 0; rr < 16; rr++) t0 += s_red[rr][tid];
        atomicAdd(&g_sq[tid], (double)t0);
    }
}

// -------------------------------- BN finalize --------------------------------
__global__ void k_finalize(const float* __restrict__ g, const float* __restrict__ be,
                           int off, int C) {
    int c = threadIdx.x;
    if (c < C) {
        const double invM = 1.0 / (double)M_ROWS;
        double m = g_sum[off + c] * invM;
        double v = g_sq[off + c] * invM - m * m;
        float rs = rsqrtf((float)v + EPSf);
        float a = g[c] * rs;
        g_a[off + c] = a;
        g_cs[off + c] = fmaf(-(float)m, a, be[c]);
    }
}

// -------------- Layer1: bn0+relu, 64->64 matmul (f32x2), stats ---------------
__global__ void __launch_bounds__(256)
k_layer1(const float* __restrict__ W1, const float* __restrict__ b1) {
    __shared__ __align__(16) float s_W[64 * 64];
    __shared__ __align__(16) float s_b[64];
    __shared__ float s_a[64], s_cs[64];
    __shared__ __align__(16) ull s_x2[32][64];
    __shared__ float s_red[16][64];
    int tid = threadIdx.x;
    for (int i = tid; i < 4096; i += 256) s_W[i] = W1[i];
    if (tid < 64) { s_b[tid] = b1[tid]; s_a[tid] = g_a[tid]; s_cs[tid] = g_cs[tid]; }
    __syncthreads();
    int rg = tid >> 4, cg = tid & 15, c0 = cg * 4;
    int r0 = rg * 2;
    ulonglong2 bp = *reinterpret_cast<const ulonglong2*>(&s_b[c0]);
    ull ls01 = 0, ls23 = 0, lq01 = 0, lq23 = 0;

    for (int t = 0; t < 4; t++) {
        int row0 = (blockIdx.x * 4 + t) * 32;
#pragma unroll
        for (int e = 0; e < 4; e++) {
            int lin = e * 256 + tid;
            int rr = lin >> 5, jj = (lin & 31) * 2;
            float2 v = *reinterpret_cast<const float2*>(&g_h0[(size_t)(row0 + rr) * 64 + jj]);
            float v0 = fmaxf(fmaf(v.x, s_a[jj],     s_cs[jj]),     0.f);
            float v1 = fmaxf(fmaf(v.y, s_a[jj + 1], s_cs[jj + 1]), 0.f);
            ulonglong2 st; st.x = pack2(v0, v0); st.y = pack2(v1, v1);
            *reinterpret_cast<ulonglong2*>(&s_x2[rr][jj]) = st;
        }
        __syncthreads();
        ull a01_0 = bp.x, a23_0 = bp.y, a01_1 = bp.x, a23_1 = bp.y;
#pragma unroll
        for (int j = 0; j < 64; j++) {
            ull x0 = s_x2[r0][j], x1 = s_x2[r0 + 1][j];
            ulonglong2 w = *reinterpret_cast<const ulonglong2*>(&s_W[j * 64 + c0]);
            a01_0 = fma2(x0, w.x, a01_0); a23_0 = fma2(x0, w.y, a23_0);
            a01_1 = fma2(x1, w.x, a01_1); a23_1 = fma2(x1, w.y, a23_1);
        }
        ulonglong2 o;
        o.x = a01_0; o.y = a23_0;
        *reinterpret_cast<ulonglong2*>(&g_h1[(size_t)(row0 + r0) * 64 + c0]) = o;
        o.x = a01_1; o.y = a23_1;
        *reinterpret_cast<ulonglong2*>(&g_h1[(size_t)(row0 + r0 + 1) * 64 + c0]) = o;
        ls01 = add2(add2(ls01, a01_0), a01_1);
        ls23 = add2(add2(ls23, a23_0), a23_1);
        lq01 = fma2(a01_0, a01_0, lq01); lq01 = fma2(a01_1, a01_1, lq01);
        lq23 = fma2(a23_0, a23_0, lq23); lq23 = fma2(a23_1, a23_1, lq23);
        __syncthreads();
    }
    float l0, l1, l2, l3;
    unpack2(ls01, l0, l1); unpack2(ls23, l2, l3);
    s_red[rg][c0] = l0; s_red[rg][c0+1] = l1; s_red[rg][c0+2] = l2; s_red[rg][c0+3] = l3;
    __syncthreads();
    if (tid < 64) {
        float t0 = 0.f;
#pragma unroll
        for (int rr = 0; rr < 16; rr++) t0 += s_red[rr][tid];
        atomicAdd(&g_sum[64 + tid], (double)t0);
    }
    __syncthreads();
    unpack2(lq01, l0, l1); unpack2(lq23, l2, l3);
    s_red[rg][c0] = l0; s_red[rg][c0+1] = l1; s_red[rg][c0+2] = l2; s_red[rg][c0+3] = l3;
    __syncthreads();
    if (tid < 64) {
        float t0 = 0.f;
#pragma unroll
        for (int rr = 0; rr < 16; rr++) t0 += s_red[rr][tid];
        atomicAdd(&g_sq[64 + tid], (double)t0);
    }
}

// ------ Layer2: bn1+relu, 64->128 matmul (f32x2), stats, fused max/min ------
// Tile = 16 rows; a query (32 rows) = 2 consecutive tiles of the same block.
// h2 is never materialized: raw per-query max/min are reduced in shared memory.
__global__ void __launch_bounds__(256)
k_layer2(const float* __restrict__ W2, const float* __restrict__ b2) {
    __shared__ __align__(16) float s_W[64 * 128];     // 32 KB
    __shared__ __align__(16) float s_b[128];
    __shared__ float s_a[64], s_cs[64];
    __shared__ __align__(16) ull s_x2[16][64];        // 8 KB
    __shared__ float s_red[8][128];                   // 4 KB
    int tid = threadIdx.x;
    for (int i = tid; i < 8192; i += 256) s_W[i] = W2[i];
    if (tid < 128) s_b[tid] = b2[tid];
    if (tid < 64) { s_a[tid] = g_a[64 + tid]; s_cs[tid] = g_cs[64 + tid]; }
    __syncthreads();
    int rg = tid >> 5, cg = tid & 31, c0 = cg * 4;
    int r0 = rg * 2;
    ulonglong2 bp = *reinterpret_cast<const ulonglong2*>(&s_b[c0]);
    ull ls01 = 0, ls23 = 0, lq01 = 0, lq23 = 0;
    float mx0 = -3.402823466e38f, mx1 = mx0, mx2 = mx0, mx3 = mx0;
    float mn0 =  3.402823466e38f, mn1 = mn0, mn2 = mn0, mn3 = mn0;

    for (int t = 0; t < 8; t++) {
        int row0 = (blockIdx.x * 8 + t) * 16;
#pragma unroll
        for (int e = 0; e < 2; e++) {
            int lin = e * 256 + tid;
            int rr = lin >> 5, jj = (lin & 31) * 2;
            float2 v = *reinterpret_cast<const float2*>(&g_h1[(size_t)(row0 + rr) * 64 + jj]);
            float v0 = fmaxf(fmaf(v.x, s_a[jj],     s_cs[jj]),     0.f);
            float v1 = fmaxf(fmaf(v.y, s_a[jj + 1], s_cs[jj + 1]), 0.f);
            ulonglong2 st; st.x = pack2(v0, v0); st.y = pack2(v1, v1);
            *reinterpret_cast<ulonglong2*>(&s_x2[rr][jj]) = st;
        }
        __syncthreads();
        ull a01_0 = bp.x, a23_0 = bp.y, a01_1 = bp.x, a23_1 = bp.y;
#pragma unroll
        for (int j = 0; j < 64; j++) {
            ull x0 = s_x2[r0][j], x1 = s_x2[r0 + 1][j];
            ulonglong2 w = *reinterpret_cast<const ulonglong2*>(&s_W[j * 128 + c0]);
            a01_0 = fma2(x0, w.x, a01_0); a23_0 = fma2(x0, w.y, a23_0);
            a01_1 = fma2(x1, w.x, a01_1); a23_1 = fma2(x1, w.y, a23_1);
        }
        ls01 = add2(add2(ls01, a01_0), a01_1);
        ls23 = add2(add2(ls23, a23_0), a23_1);
        lq01 = fma2(a01_0, a01_0, lq01); lq01 = fma2(a01_1, a01_1, lq01);
        lq23 = fma2(a23_0, a23_0, lq23); lq23 = fma2(a23_1, a23_1, lq23);

        float e0, e1, e2, e3, f0, f1, f2, f3;
        unpack2(a01_0, e0, e1); unpack2(a23_0, e2, e3);
        unpack2(a01_1, f0, f1); unpack2(a23_1, f2, f3);
        mx0 = fmaxf(mx0, fmaxf(e0, f0)); mn0 = fminf(mn0, fminf(e0, f0));
        mx1 = fmaxf(mx1, fmaxf(e1, f1)); mn1 = fminf(mn1, fminf(e1, f1));
        mx2 = fmaxf(mx2, fmaxf(e2, f2)); mn2 = fminf(mn2, fminf(e2, f2));
        mx3 = fmaxf(mx3, fmaxf(e3, f3)); mn3 = fminf(mn3, fminf(e3, f3));

        if (t & 1) {  // flush query q (32 rows complete)
            int q = blockIdx.x * 4 + (t >> 1);
            s_red[rg][c0] = mx0; s_red[rg][c0+1] = mx1; s_red[rg][c0+2] = mx2; s_red[rg][c0+3] = mx3;
            __syncthreads();
            if (tid < 128) {
                float m = s_red[0][tid];
#pragma unroll
                for (int rr = 1; rr < 8; rr++) m = fmaxf(m, s_red[rr][tid]);
                g_mx[(size_t)q * 128 + tid] = m;
            }
            __syncthreads();
            s_red[rg][c0] = mn0; s_red[rg][c0+1] = mn1; s_red[rg][c0+2] = mn2; s_red[rg][c0+3] = mn3;
            __syncthreads();
            if (tid < 128) {
                float m = s_red[0][tid];
#pragma unroll
                for (int rr = 1; rr < 8; rr++) m = fminf(m, s_red[rr][tid]);
                g_mn[(size_t)q * 128 + tid] = m;
            }
            mx0 = mx1 = mx2 = mx3 = -3.402823466e38f;
            mn0 = mn1 = mn2 = mn3 =  3.402823466e38f;
        }
        __syncthreads();
    }
    float l0, l1, l2, l3;
    unpack2(ls01, l0, l1); unpack2(ls23, l2, l3);
    s_red[rg][c0] = l0; s_red[rg][c0+1] = l1; s_red[rg][c0+2] = l2; s_red[rg][c0+3] = l3;
    __syncthreads();
    if (tid < 128) {
        float t0 = 0.f;
#pragma unroll
        for (int rr = 0; rr < 8; rr++) t0 += s_red[rr][tid];
        atomicAdd(&g_sum[128 + tid], (double)t0);
    }
    __syncthreads();
    unpack2(lq01, l0, l1); unpack2(lq23, l2, l3);
    s_red[rg][c0] = l0; s_red[rg][c0+1] = l1; s_red[rg][c0+2] = l2; s_red[rg][c0+3] = l3;
    __syncthreads();
    if (tid < 128) {
        float t0 = 0.f;
#pragma unroll
        for (int rr = 0; rr < 8; rr++) t0 += s_red[rr][tid];
        atomicAdd(&g_sq[128 + tid], (double)t0);
    }
}

// --------- Final: BN2+relu applied to per-query max/min (exact fusion) -------
__global__ void __launch_bounds__(256)
k_out(float* __restrict__ out) {
    int i = blockIdx.x * 256 + threadIdx.x;   // i < B*S*128
    int c = i & 127;
    float a = g_a[128 + c], cs = g_cs[128 + c];
    float v = (a >= 0.f) ? g_mx[i] : g_mn[i];
    out[(size_t)BB * SS * 3 + i] = fmaxf(fmaf(v, a, cs), 0.f);
}

// -----------------------------------------------------------------------------
extern "C" void kernel_launch(void* const* d_in, const int* in_sizes, int n_in,
                              void* d_out, int out_size) {
    const float* xyz    = (const float*)d_in[0];
    const float* points = (const float*)d_in[1];
    const float* W0 = (const float*)d_in[2];  const float* b0 = (const float*)d_in[3];
    const float* g0 = (const float*)d_in[4];  const float* be0 = (const float*)d_in[5];
    const float* W1 = (const float*)d_in[6];  const float* b1 = (const float*)d_in[7];
    const float* g1 = (const float*)d_in[8];  const float* be1 = (const float*)d_in[9];
    const float* W2 = (const float*)d_in[10]; const float* b2 = (const float*)d_in[11];
    const float* g2 = (const float*)d_in[12]; const float* be2 = (const float*)d_in[13];
    float* out = (float*)d_out;   // [B*S*3 new_xyz | B*S*128 new_points]

    k_init<<<1, 256>>>();
    k_fps<<<BB, 1024>>>(xyz, out);
    k_ball<<<(BB * SS) / 8, 256>>>(xyz, out);
    k_layer0<<<2048, 256>>>(points, xyz, out, W0, b0);
    k_finalize<<<1, 64>>>(g0, be0, 0, 64);
    k_layer1<<<2048, 256>>>(W1, b1);
    k_finalize<<<1, 64>>>(g1, be1, 64, 64);
    k_layer2<<<2048, 256>>>(W2, b2);
    k_finalize<<<1, 128>>>(g2, be2, 128, 128);
    k_out<<<(BB * SS * 128) / 256, 256>>>(out);
}

// round 12
// speedup vs baseline: 1.4090x; 1.1396x over previous
#include <cuda_runtime.h>
#include <cstdint>

#define BB 8
#define NN 8192
#define SS 1024
#define KK 32
static constexpr int M_ROWS = BB * SS * KK;   // 262144
static constexpr float EPSf = 1e-5f;

typedef unsigned long long ull;

// ---------------- packed f32x2 helpers (rn — bit-identical to scalar) -------
__device__ __forceinline__ ull pack2(float lo, float hi) {
    ull v; asm("mov.b64 %0, {%1, %2};" : "=l"(v) : "f"(lo), "f"(hi)); return v;
}
__device__ __forceinline__ void unpack2(ull v, float& lo, float& hi) {
    asm("mov.b64 {%0, %1}, %2;" : "=f"(lo), "=f"(hi) : "l"(v));
}
__device__ __forceinline__ ull add2(ull a, ull b) {
    ull d; asm("add.rn.f32x2 %0, %1, %2;" : "=l"(d) : "l"(a), "l"(b)); return d;
}
__device__ __forceinline__ ull mul2(ull a, ull b) {
    ull d; asm("mul.rn.f32x2 %0, %1, %2;" : "=l"(d) : "l"(a), "l"(b)); return d;
}
__device__ __forceinline__ ull fma2(ull a, ull b, ull c) {
    ull d; asm("fma.rn.f32x2 %0, %1, %2, %3;" : "=l"(d) : "l"(a), "l"(b), "l"(c)); return d;
}

// ------------------------------ device scratch ------------------------------
__device__ float  g_h0[(size_t)M_ROWS * 64];     // layer0 pre-BN   64 MB
__device__ float  g_h1[(size_t)M_ROWS * 64];     // layer1 pre-BN   64 MB
__device__ float  g_mx[(size_t)BB * SS * 128];   // per-query raw max (layer2)
__device__ float  g_mn[(size_t)BB * SS * 128];   // per-query raw min (layer2)
__device__ int    g_gidx[M_ROWS];
__device__ double g_sum[256];
__device__ double g_sq[256];
__device__ float  g_a[256];
__device__ float  g_cs[256];

__global__ void k_init() {
    int i = threadIdx.x;
    if (i < 256) { g_sum[i] = 0.0; g_sq[i] = 0.0; }
}

// -------------------------- FPS: one CTA per batch ---------------------------
// Packed-f32x2 distance update (exact rn semantics). Per-thread best via an
// FMNMX tree (no per-point index tracking); the (value, tid) pair reduces via
// REDUX max/min (tid order == point-index order since base = tid*8); only the
// winning thread scans its 8 register dists for the first bits==m to recover j
// and broadcasts the centroid from registers. Selection identical to before.
__global__ void __launch_bounds__(1024, 1)
k_fps(const float* __restrict__ xyz, float* __restrict__ out) {
    int b = blockIdx.x;
    const float* X = xyz + (size_t)b * NN * 3;
    int tid = threadIdx.x;
    int base = tid * 8;

    const float4* Xv = (const float4*)(X + (size_t)base * 3);
    float4 v0 = Xv[0], v1 = Xv[1], v2 = Xv[2], v3 = Xv[3], v4 = Xv[4], v5 = Xv[5];
    float px[8], py[8], pz[8];
    px[0]=v0.x; py[0]=v0.y; pz[0]=v0.z;  px[1]=v0.w; py[1]=v1.x; pz[1]=v1.y;
    px[2]=v1.z; py[2]=v1.w; pz[2]=v2.x;  px[3]=v2.y; py[3]=v2.z; pz[3]=v2.w;
    px[4]=v3.x; py[4]=v3.y; pz[4]=v3.z;  px[5]=v3.w; py[5]=v4.x; pz[5]=v4.y;
    px[6]=v4.z; py[6]=v4.w; pz[6]=v5.x;  px[7]=v5.y; py[7]=v5.z; pz[7]=v5.w;

    ull pxp0=pack2(px[0],px[1]), pxp1=pack2(px[2],px[3]), pxp2=pack2(px[4],px[5]), pxp3=pack2(px[6],px[7]);
    ull pyp0=pack2(py[0],py[1]), pyp1=pack2(py[2],py[3]), pyp2=pack2(py[4],py[5]), pyp3=pack2(py[6],py[7]);
    ull pzp0=pack2(pz[0],pz[1]), pzp1=pack2(pz[2],pz[3]), pzp2=pack2(pz[4],pz[5]), pzp3=pack2(pz[6],pz[7]);

    float dist[8];
#pragma unroll
    for (int j = 0; j < 8; j++) dist[j] = 1e10f;

    __shared__ float4 s_c;
    __shared__ ull    s_key[32];
    int lane = tid & 31;
    int warp = tid >> 5;

    if (tid == 0) {
        s_c = make_float4(px[0], py[0], pz[0], 0.f);
        float* o = out + (size_t)b * SS * 3;
        o[0] = px[0]; o[1] = py[0]; o[2] = pz[0];
    }
    __syncthreads();

    for (int s = 1; s < SS; s++) {
        float4 c = s_c;                       // broadcast LDS.128
        ull cxn = pack2(-c.x, -c.x), cyn = pack2(-c.y, -c.y), czn = pack2(-c.z, -c.z);

#define FPS_STEP(P, PX, PY, PZ)                                             \
        {                                                                    \
            ull dx = add2(PX, cxn), dy = add2(PY, cyn), dz = add2(PZ, czn);  \
            ull d  = add2(add2(mul2(dx, dx), mul2(dy, dy)), mul2(dz, dz));   \
            float da, db; unpack2(d, da, db);                                \
            dist[2*P]   = fminf(dist[2*P],   da);                            \
            dist[2*P+1] = fminf(dist[2*P+1], db);                            \
        }
        FPS_STEP(0, pxp0, pyp0, pzp0)
        FPS_STEP(1, pxp1, pyp1, pzp1)
        FPS_STEP(2, pxp2, pyp2, pzp2)
        FPS_STEP(3, pxp3, pyp3, pzp3)
#undef FPS_STEP

        // per-thread max (value only) via FMNMX tree
        float m01 = fmaxf(dist[0], dist[1]);
        float m23 = fmaxf(dist[2], dist[3]);
        float m45 = fmaxf(dist[4], dist[5]);
        float m67 = fmaxf(dist[6], dist[7]);
        float best = fmaxf(fmaxf(m01, m23), fmaxf(m45, m67));

        // stage 1: warp (value, min-tid) — dist>=0 so float order == uint order
        unsigned bb   = __float_as_uint(best);
        unsigned m    = __reduce_max_sync(0xffffffffu, bb);
        unsigned cand = (bb == m) ? (unsigned)tid : 0xffffffffu;
        unsigned mi   = __reduce_min_sync(0xffffffffu, cand);
        if (lane == 0) s_key[warp] = ((ull)m << 32) | (ull)mi;
        __syncthreads();

        // stage 2: all warps redundantly reduce over 32 warp keys
        ull k = s_key[lane];
        unsigned wb = (unsigned)(k >> 32), wi = (unsigned)k;
        unsigned m2 = __reduce_max_sync(0xffffffffu, wb);
        unsigned c2 = (wb == m2) ? wi : 0xffffffffu;
        unsigned t2 = __reduce_min_sync(0xffffffffu, c2);

        if ((unsigned)tid == t2) {
            // first j (ascending) with dist bits == m2
            int j = 0;
#pragma unroll
            for (int jj = 7; jj >= 0; jj--)
                if (__float_as_uint(dist[jj]) == m2) j = jj;
            int p = j >> 1;
            ull vx = (p == 0) ? pxp0 : (p == 1) ? pxp1 : (p == 2) ? pxp2 : pxp3;
            ull vy = (p == 0) ? pyp0 : (p == 1) ? pyp1 : (p == 2) ? pyp2 : pyp3;
            ull vz = (p == 0) ? pzp0 : (p == 1) ? pzp1 : (p == 2) ? pzp2 : pzp3;
            float xl, xh, yl, yh, zl, zh;
            unpack2(vx, xl, xh); unpack2(vy, yl, yh); unpack2(vz, zl, zh);
            float X0 = (j & 1) ? xh : xl;
            float Y0 = (j & 1) ? yh : yl;
            float Z0 = (j & 1) ? zh : zl;
            s_c = make_float4(X0, Y0, Z0, 0.f);
            float* o = out + ((size_t)b * SS + s) * 3;
            o[0] = X0; o[1] = Y0; o[2] = Z0;
        }
        __syncthreads();
    }
}

// ------------------------ Ball query: one warp per query ---------------------
__global__ void __launch_bounds__(256)
k_ball(const float* __restrict__ xyz, const float* __restrict__ newxyz) {
    const float R2 = (float)(0.2 * 0.2);
    int warp = threadIdx.x >> 5, lane = threadIdx.x & 31;
    int q = blockIdx.x * 8 + warp;
    int b = q >> 10;
    const float* X = xyz + (size_t)b * NN * 3;
    float nx = newxyz[q * 3], ny = newxyz[q * 3 + 1], nz = newxyz[q * 3 + 2];
    float s2 = __fadd_rn(__fadd_rn(__fmul_rn(nx, nx), __fmul_rn(ny, ny)),
                         __fmul_rn(nz, nz));
    __shared__ int s_list[8][KK];
    int found = 0;
    for (int basep = 0; basep < NN; basep += 32) {
        int n = basep + lane;
        float x = X[n * 3], y = X[n * 3 + 1], z = X[n * 3 + 2];
        float n2  = __fadd_rn(__fadd_rn(__fmul_rn(x, x), __fmul_rn(y, y)),
                              __fmul_rn(z, z));
        float dot = __fadd_rn(__fadd_rn(__fmul_rn(nx, x), __fmul_rn(ny, y)),
                              __fmul_rn(nz, z));
        float sq  = __fsub_rn(__fadd_rn(s2, n2), __fmul_rn(2.0f, dot));
        bool pass = !(sq > R2);
        unsigned msk = __ballot_sync(0xffffffffu, pass);
        int pos = found + __popc(msk & ((1u << lane) - 1u));
        if (pass && pos < KK) s_list[warp][pos] = n;
        found += __popc(msk);
        if (found >= KK) break;
    }
    __syncwarp();
    int cnt = found < KK ? found : KK;
    int first = s_list[warp][0];
    int v = (lane < cnt) ? s_list[warp][lane] : first;
    g_gidx[q * KK + lane] = v;
}

// ---------------- Layer0: gather + 9->64 matmul (f32x2) + stats --------------
// Indices preloaded to smem; feature tile double-buffered (1 barrier/tile);
// tile t+1 feature LDGs issued in registers while GEMM(t) runs.
__global__ void __launch_bounds__(256)
k_layer0(const float* __restrict__ points, const float* __restrict__ xyz,
         const float* __restrict__ newxyz, const float* __restrict__ W0,
         const float* __restrict__ b0) {
    __shared__ __align__(16) float s_W[9 * 64];
    __shared__ __align__(16) float s_b[64];
    __shared__ __align__(16) int   s_idx[128];
    __shared__ __align__(16) ull   s_f2[2][16][9];
    __shared__ float s_red[16][64];
    int tid = threadIdx.x;
    int row0 = blockIdx.x * 128;
    for (int i = tid; i < 576; i += 256) s_W[i] = W0[i];
    if (tid < 64) s_b[tid] = b0[tid];
    if (tid < 32) *reinterpret_cast<int4*>(&s_idx[tid * 4]) =
        *reinterpret_cast<const int4*>(&g_gidx[row0 + tid * 4]);
    __syncthreads();

    int r = tid >> 4, cg = tid & 15, c0 = cg * 4;
    ulonglong2 bp = *reinterpret_cast<const ulonglong2*>(&s_b[c0]);
    ull ls01 = 0, ls23 = 0, lq01 = 0, lq23 = 0;

    const bool ld = tid < 144;
    int lrr = tid / 9, lj = tid - lrr * 9;
    const int bidx = row0 >> 15;                 // batch (constant per CTA)

    auto load_feat = [&](int t) -> float {
        int row = row0 + t * 16 + lrr;
        int i = s_idx[t * 16 + lrr];
        if (lj < 6) {
            return points[((size_t)bidx * NN + i) * 6 + lj];
        } else {
            int q = row >> 5, cc = lj - 6;
            return xyz[((size_t)bidx * NN + i) * 3 + cc] - newxyz[(size_t)q * 3 + cc];
        }
    };

    float fcur = 0.f;
    if (ld) fcur = load_feat(0);

    for (int t = 0; t < 8; t++) {
        if (ld) s_f2[t & 1][lrr][lj] = pack2(fcur, fcur);
        __syncthreads();
        if (ld && t < 7) fcur = load_feat(t + 1);   // overlap next tile's LDG

        ull a01 = bp.x, a23 = bp.y;
#pragma unroll
        for (int j = 0; j < 9; j++) {
            ull f = s_f2[t & 1][r][j];
            ulonglong2 w = *reinterpret_cast<const ulonglong2*>(&s_W[j * 64 + c0]);
            a01 = fma2(f, w.x, a01);
            a23 = fma2(f, w.y, a23);
        }
        ulonglong2 o; o.x = a01; o.y = a23;
        *reinterpret_cast<ulonglong2*>(&g_h0[(size_t)(row0 + t * 16 + r) * 64 + c0]) = o;
        ls01 = add2(ls01, a01); ls23 = add2(ls23, a23);
        lq01 = fma2(a01, a01, lq01); lq23 = fma2(a23, a23, lq23);
    }
    float l0, l1, l2, l3;
    unpack2(ls01, l0, l1); unpack2(ls23, l2, l3);
    s_red[r][c0] = l0; s_red[r][c0+1] = l1; s_red[r][c0+2] = l2; s_red[r][c0+3] = l3;
    __syncthreads();
    if (tid < 64) {
        float t0 = 0.f;
#pragma unroll
        for (int rr = 0; rr < 16; rr++) t0 += s_red[rr][tid];
        atomicAdd(&g_sum[tid], (double)t0);
    }
    __syncthreads();
    unpack2(lq01, l0, l1); unpack2(lq23, l2, l3);
    s_red[r][c0] = l0; s_red[r][c0+1] = l1; s_red[r][c0+2] = l2; s_red[r][c0+3] = l3;
    __syncthreads();
    if (tid < 64) {
        float t0 = 0.f;
#pragma unroll
        for (int rr = 0; rr < 16; rr++) t0 += s_red[rr][tid];
        atomicAdd(&g_sq[tid], (double)t0);
    }
}

// -------------------------------- BN finalize --------------------------------
__global__ void k_finalize(const float* __restrict__ g, const float* __restrict__ be,
                           int off, int C) {
    int c = threadIdx.x;
    if (c < C) {
        const double invM = 1.0 / (double)M_ROWS;
        double m = g_sum[off + c] * invM;
        double v = g_sq[off + c] * invM - m * m;
        float rs = rsqrtf((float)v + EPSf);
        float a = g[c] * rs;
        g_a[off + c] = a;
        g_cs[off + c] = fmaf(-(float)m, a, be[c]);
    }
}

// -------------- Layer1: bn0+relu, 64->64 matmul (f32x2), stats ---------------
__global__ void __launch_bounds__(256)
k_layer1(const float* __restrict__ W1, const float* __restrict__ b1) {
    __shared__ __align__(16) float s_W[64 * 64];
    __shared__ __align__(16) float s_b[64];
    __shared__ float s_a[64], s_cs[64];
    __shared__ __align__(16) ull s_x2[32][64];
    __shared__ float s_red[16][64];
    int tid = threadIdx.x;
    for (int i = tid; i < 4096; i += 256) s_W[i] = W1[i];
    if (tid < 64) { s_b[tid] = b1[tid]; s_a[tid] = g_a[tid]; s_cs[tid] = g_cs[tid]; }
    __syncthreads();
    int rg = tid >> 4, cg = tid & 15, c0 = cg * 4;
    int r0 = rg * 2;
    ulonglong2 bp = *reinterpret_cast<const ulonglong2*>(&s_b[c0]);
    ull ls01 = 0, ls23 = 0, lq01 = 0, lq23 = 0;

    for (int t = 0; t < 4; t++) {
        int row0 = (blockIdx.x * 4 + t) * 32;
#pragma unroll
        for (int e = 0; e < 4; e++) {
            int lin = e * 256 + tid;
            int rr = lin >> 5, jj = (lin & 31) * 2;
            float2 v = *reinterpret_cast<const float2*>(&g_h0[(size_t)(row0 + rr) * 64 + jj]);
            float v0 = fmaxf(fmaf(v.x, s_a[jj],     s_cs[jj]),     0.f);
            float v1 = fmaxf(fmaf(v.y, s_a[jj + 1], s_cs[jj + 1]), 0.f);
            ulonglong2 st; st.x = pack2(v0, v0); st.y = pack2(v1, v1);
            *reinterpret_cast<ulonglong2*>(&s_x2[rr][jj]) = st;
        }
        __syncthreads();
        ull a01_0 = bp.x, a23_0 = bp.y, a01_1 = bp.x, a23_1 = bp.y;
#pragma unroll
        for (int j = 0; j < 64; j++) {
            ull x0 = s_x2[r0][j], x1 = s_x2[r0 + 1][j];
            ulonglong2 w = *reinterpret_cast<const ulonglong2*>(&s_W[j * 64 + c0]);
            a01_0 = fma2(x0, w.x, a01_0); a23_0 = fma2(x0, w.y, a23_0);
            a01_1 = fma2(x1, w.x, a01_1); a23_1 = fma2(x1, w.y, a23_1);
        }
        ulonglong2 o;
        o.x = a01_0; o.y = a23_0;
        *reinterpret_cast<ulonglong2*>(&g_h1[(size_t)(row0 + r0) * 64 + c0]) = o;
        o.x = a01_1; o.y = a23_1;
        *reinterpret_cast<ulonglong2*>(&g_h1[(size_t)(row0 + r0 + 1) * 64 + c0]) = o;
        ls01 = add2(add2(ls01, a01_0), a01_1);
        ls23 = add2(add2(ls23, a23_0), a23_1);
        lq01 = fma2(a01_0, a01_0, lq01); lq01 = fma2(a01_1, a01_1, lq01);
        lq23 = fma2(a23_0, a23_0, lq23); lq23 = fma2(a23_1, a23_1, lq23);
        __syncthreads();
    }
    float l0, l1, l2, l3;
    unpack2(ls01, l0, l1); unpack2(ls23, l2, l3);
    s_red[rg][c0] = l0; s_red[rg][c0+1] = l1; s_red[rg][c0+2] = l2; s_red[rg][c0+3] = l3;
    __syncthreads();
    if (tid < 64) {
        float t0 = 0.f;
#pragma unroll
        for (int rr = 0; rr < 16; rr++) t0 += s_red[rr][tid];
        atomicAdd(&g_sum[64 + tid], (double)t0);
    }
    __syncthreads();
    unpack2(lq01, l0, l1); unpack2(lq23, l2, l3);
    s_red[rg][c0] = l0; s_red[rg][c0+1] = l1; s_red[rg][c0+2] = l2; s_red[rg][c0+3] = l3;
    __syncthreads();
    if (tid < 64) {
        float t0 = 0.f;
#pragma unroll
        for (int rr = 0; rr < 16; rr++) t0 += s_red[rr][tid];
        atomicAdd(&g_sq[64 + tid], (double)t0);
    }
}

// ------ Layer2: bn1+relu, 64->128 matmul (f32x2), stats, fused max/min ------
__global__ void __launch_bounds__(256)
k_layer2(const float* __restrict__ W2, const float* __restrict__ b2) {
    __shared__ __align__(16) float s_W[64 * 128];
    __shared__ __align__(16) float s_b[128];
    __shared__ float s_a[64], s_cs[64];
    __shared__ __align__(16) ull s_x2[16][64];
    __shared__ float s_red[8][128];
    int tid = threadIdx.x;
    for (int i = tid; i < 8192; i += 256) s_W[i] = W2[i];
    if (tid < 128) s_b[tid] = b2[tid];
    if (tid < 64) { s_a[tid] = g_a[64 + tid]; s_cs[tid] = g_cs[64 + tid]; }
    __syncthreads();
    int rg = tid >> 5, cg = tid & 31, c0 = cg * 4;
    int r0 = rg * 2;
    ulonglong2 bp = *reinterpret_cast<const ulonglong2*>(&s_b[c0]);
    ull ls01 = 0, ls23 = 0, lq01 = 0, lq23 = 0;
    float mx0 = -3.402823466e38f, mx1 = mx0, mx2 = mx0, mx3 = mx0;
    float mn0 =  3.402823466e38f, mn1 = mn0, mn2 = mn0, mn3 = mn0;

    for (int t = 0; t < 8; t++) {
        int row0 = (blockIdx.x * 8 + t) * 16;
#pragma unroll
        for (int e = 0; e < 2; e++) {
            int lin = e * 256 + tid;
            int rr = lin >> 5, jj = (lin & 31) * 2;
            float2 v = *reinterpret_cast<const float2*>(&g_h1[(size_t)(row0 + rr) * 64 + jj]);
            float v0 = fmaxf(fmaf(v.x, s_a[jj],     s_cs[jj]),     0.f);
            float v1 = fmaxf(fmaf(v.y, s_a[jj + 1], s_cs[jj + 1]), 0.f);
            ulonglong2 st; st.x = pack2(v0, v0); st.y = pack2(v1, v1);
            *reinterpret_cast<ulonglong2*>(&s_x2[rr][jj]) = st;
        }
        __syncthreads();
        ull a01_0 = bp.x, a23_0 = bp.y, a01_1 = bp.x, a23_1 = bp.y;
#pragma unroll
        for (int j = 0; j < 64; j++) {
            ull x0 = s_x2[r0][j], x1 = s_x2[r0 + 1][j];
            ulonglong2 w = *reinterpret_cast<const ulonglong2*>(&s_W[j * 128 + c0]);
            a01_0 = fma2(x0, w.x, a01_0); a23_0 = fma2(x0, w.y, a23_0);
            a01_1 = fma2(x1, w.x, a01_1); a23_1 = fma2(x1, w.y, a23_1);
        }
        ls01 = add2(add2(ls01, a01_0), a01_1);
        ls23 = add2(add2(ls23, a23_0), a23_1);
        lq01 = fma2(a01_0, a01_0, lq01); lq01 = fma2(a01_1, a01_1, lq01);
        lq23 = fma2(a23_0, a23_0, lq23); lq23 = fma2(a23_1, a23_1, lq23);

        float e0, e1, e2, e3, f0, f1, f2, f3;
        unpack2(a01_0, e0, e1); unpack2(a23_0, e2, e3);
        unpack2(a01_1, f0, f1); unpack2(a23_1, f2, f3);
        mx0 = fmaxf(mx0, fmaxf(e0, f0)); mn0 = fminf(mn0, fminf(e0, f0));
        mx1 = fmaxf(mx1, fmaxf(e1, f1)); mn1 = fminf(mn1, fminf(e1, f1));
        mx2 = fmaxf(mx2, fmaxf(e2, f2)); mn2 = fminf(mn2, fminf(e2, f2));
        mx3 = fmaxf(mx3, fmaxf(e3, f3)); mn3 = fminf(mn3, fminf(e3, f3));

        if (t & 1) {
            int q = blockIdx.x * 4 + (t >> 1);
            s_red[rg][c0] = mx0; s_red[rg][c0+1] = mx1; s_red[rg][c0+2] = mx2; s_red[rg][c0+3] = mx3;
            __syncthreads();
            if (tid < 128) {
                float m = s_red[0][tid];
#pragma unroll
                for (int rr = 1; rr < 8; rr++) m = fmaxf(m, s_red[rr][tid]);
                g_mx[(size_t)q * 128 + tid] = m;
            }
            __syncthreads();
            s_red[rg][c0] = mn0; s_red[rg][c0+1] = mn1; s_red[rg][c0+2] = mn2; s_red[rg][c0+3] = mn3;
            __syncthreads();
            if (tid < 128) {
                float m = s_red[0][tid];
#pragma unroll
                for (int rr = 1; rr < 8; rr++) m = fminf(m, s_red[rr][tid]);
                g_mn[(size_t)q * 128 + tid] = m;
            }
            mx0 = mx1 = mx2 = mx3 = -3.402823466e38f;
            mn0 = mn1 = mn2 = mn3 =  3.402823466e38f;
        }
        __syncthreads();
    }
    float l0, l1, l2, l3;
    unpack2(ls01, l0, l1); unpack2(ls23, l2, l3);
    s_red[rg][c0] = l0; s_red[rg][c0+1] = l1; s_red[rg][c0+2] = l2; s_red[rg][c0+3] = l3;
    __syncthreads();
    if (tid < 128) {
        float t0 = 0.f;
#pragma unroll
        for (int rr = 0; rr < 8; rr++) t0 += s_red[rr][tid];
        atomicAdd(&g_sum[128 + tid], (double)t0);
    }
    __syncthreads();
    unpack2(lq01, l0, l1); unpack2(lq23, l2, l3);
    s_red[rg][c0] = l0; s_red[rg][c0+1] = l1; s_red[rg][c0+2] = l2; s_red[rg][c0+3] = l3;
    __syncthreads();
    if (tid < 128) {
        float t0 = 0.f;
#pragma unroll
        for (int rr = 0; rr < 8; rr++) t0 += s_red[rr][tid];
        atomicAdd(&g_sq[128 + tid], (double)t0);
    }
}

// --------- Final: BN2+relu applied to per-query max/min (exact fusion) -------
__global__ void __launch_bounds__(256)
k_out(float* __restrict__ out) {
    int i = blockIdx.x * 256 + threadIdx.x;
    int c = i & 127;
    float a = g_a[128 + c], cs = g_cs[128 + c];
    float v = (a >= 0.f) ? g_mx[i] : g_mn[i];
    out[(size_t)BB * SS * 3 + i] = fmaxf(fmaf(v, a, cs), 0.f);
}

// -----------------------------------------------------------------------------
extern "C" void kernel_launch(void* const* d_in, const int* in_sizes, int n_in,
                              void* d_out, int out_size) {
    const float* xyz    = (const float*)d_in[0];
    const float* points = (const float*)d_in[1];
    const float* W0 = (const float*)d_in[2];  const float* b0 = (const float*)d_in[3];
    const float* g0 = (const float*)d_in[4];  const float* be0 = (const float*)d_in[5];
    const float* W1 = (const float*)d_in[6];  const float* b1 = (const float*)d_in[7];
    const float* g1 = (const float*)d_in[8];  const float* be1 = (const float*)d_in[9];
    const float* W2 = (const float*)d_in[10]; const float* b2 = (const float*)d_in[11];
    const float* g2 = (const float*)d_in[12]; const float* be2 = (const float*)d_in[13];
    float* out = (float*)d_out;   // [B*S*3 new_xyz | B*S*128 new_points]

    k_init<<<1, 256>>>();
    k_fps<<<BB, 1024>>>(xyz, out);
    k_ball<<<(BB * SS) / 8, 256>>>(xyz, out);
    k_layer0<<<2048, 256>>>(points, xyz, out, W0, b0);
    k_finalize<<<1, 64>>>(g0, be0, 0, 64);
    k_layer1<<<2048, 256>>>(W1, b1);
    k_finalize<<<1, 64>>>(g1, be1, 64, 64);
    k_layer2<<<2048, 256>>>(W2, b2);
    k_finalize<<<1, 128>>>(g2, be2, 128, 128);
    k_out<<<(BB * SS * 128) / 256, 256>>>(out);
}

// round 13
// speedup vs baseline: 1.4593x; 1.0357x over previous
#include <cuda_runtime.h>
#include <cstdint>

#define BB 8
#define NN 8192
#define SS 1024
#define KK 32
static constexpr int M_ROWS = BB * SS * KK;   // 262144
static constexpr float EPSf = 1e-5f;

typedef unsigned long long ull;

// ---------------- packed f32x2 helpers (rn — bit-identical to scalar) -------
__device__ __forceinline__ ull pack2(float lo, float hi) {
    ull v; asm("mov.b64 %0, {%1, %2};" : "=l"(v) : "f"(lo), "f"(hi)); return v;
}
__device__ __forceinline__ void unpack2(ull v, float& lo, float& hi) {
    asm("mov.b64 {%0, %1}, %2;" : "=f"(lo), "=f"(hi) : "l"(v));
}
__device__ __forceinline__ ull add2(ull a, ull b) {
    ull d; asm("add.rn.f32x2 %0, %1, %2;" : "=l"(d) : "l"(a), "l"(b)); return d;
}
__device__ __forceinline__ ull mul2(ull a, ull b) {
    ull d; asm("mul.rn.f32x2 %0, %1, %2;" : "=l"(d) : "l"(a), "l"(b)); return d;
}
__device__ __forceinline__ ull fma2(ull a, ull b, ull c) {
    ull d; asm("fma.rn.f32x2 %0, %1, %2, %3;" : "=l"(d) : "l"(a), "l"(b), "l"(c)); return d;
}

// ------------------------------ device scratch ------------------------------
__device__ float  g_h0[(size_t)M_ROWS * 64];     // layer0 pre-BN   64 MB
__device__ float  g_h1[(size_t)M_ROWS * 64];     // layer1 pre-BN   64 MB
__device__ float  g_mx[(size_t)BB * SS * 128];   // per-query raw max (layer2)
__device__ float  g_mn[(size_t)BB * SS * 128];   // per-query raw min (layer2)
__device__ int    g_gidx[M_ROWS];
__device__ double g_sum[256];
__device__ double g_sq[256];
__device__ float  g_a[256];
__device__ float  g_cs[256];

__global__ void k_init() {
    int i = threadIdx.x;
    if (i < 256) { g_sum[i] = 0.0; g_sq[i] = 0.0; }
}

// -------------------------- FPS: one CTA per batch ---------------------------
// 512 threads x 16 points. Packed-f32x2 distance update (exact rn semantics),
// value-only FMNMX argmax tree, two-stage (value, tid) reduction (tid order ==
// point-index order), winner recovers j from its register dists and publishes
// the NEGATED, PRE-PACKED centroid. Selection bit-identical to prior rounds.
__global__ void __launch_bounds__(512, 1)
k_fps(const float* __restrict__ xyz, float* __restrict__ out) {
    int b = blockIdx.x;
    const float* X = xyz + (size_t)b * NN * 3;
    int tid = threadIdx.x;
    int base = tid * 16;                         // 16 points per thread

    // load 16 points = 48 floats = 12 float4
    float f[48];
    const float4* Xv = (const float4*)(X + (size_t)base * 3);
#pragma unroll
    for (int i = 0; i < 12; i++) {
        float4 v = Xv[i];
        f[i * 4 + 0] = v.x; f[i * 4 + 1] = v.y; f[i * 4 + 2] = v.z; f[i * 4 + 3] = v.w;
    }
    ull cxp[8], cyp[8], czp[8];
#pragma unroll
    for (int g = 0; g < 8; g++) {
        cxp[g] = pack2(f[(2 * g) * 3 + 0], f[(2 * g + 1) * 3 + 0]);
        cyp[g] = pack2(f[(2 * g) * 3 + 1], f[(2 * g + 1) * 3 + 1]);
        czp[g] = pack2(f[(2 * g) * 3 + 2], f[(2 * g + 1) * 3 + 2]);
    }
    float dist[16];
#pragma unroll
    for (int j = 0; j < 16; j++) dist[j] = 1e10f;

    __shared__ __align__(16) ull s_cp[4];    // negated packed centroid {-x,-x},{-y,-y},{-z,-z}
    __shared__ ull s_key[32];                // warp keys (16 valid; 16..31 neutral 0)
    int lane = tid & 31;
    int warp = tid >> 5;                     // 0..15

    if (tid >= 16 && tid < 32) s_key[tid] = 0ull;   // neutral keys for lanes 16..31
    if (tid == 0) {
        s_cp[0] = pack2(-f[0], -f[0]);
        s_cp[1] = pack2(-f[1], -f[1]);
        s_cp[2] = pack2(-f[2], -f[2]);
        float* o = out + (size_t)b * SS * 3;
        o[0] = f[0]; o[1] = f[1]; o[2] = f[2];
    }
    __syncthreads();

    for (int s = 1; s < SS; s++) {
        ulonglong2 cp01 = *reinterpret_cast<const ulonglong2*>(&s_cp[0]);  // LDS.128
        ull cp2 = s_cp[2];                                                 // LDS.64

#pragma unroll
        for (int g = 0; g < 8; g++) {
            ull dx = add2(cxp[g], cp01.x);
            ull dy = add2(cyp[g], cp01.y);
            ull dz = add2(czp[g], cp2);
            ull d  = add2(add2(mul2(dx, dx), mul2(dy, dy)), mul2(dz, dz));
            float da, db; unpack2(d, da, db);
            dist[2 * g]     = fminf(dist[2 * g],     da);
            dist[2 * g + 1] = fminf(dist[2 * g + 1], db);
        }

        // value-only max tree over 16
        float t8[8];
#pragma unroll
        for (int g = 0; g < 8; g++) t8[g] = fmaxf(dist[2 * g], dist[2 * g + 1]);
        float t40 = fmaxf(t8[0], t8[1]), t41 = fmaxf(t8[2], t8[3]);
        float t42 = fmaxf(t8[4], t8[5]), t43 = fmaxf(t8[6], t8[7]);
        float best = fmaxf(fmaxf(t40, t41), fmaxf(t42, t43));

        // stage 1: warp (value, min tid) — dist>=0 so float order == uint order
        unsigned bb   = __float_as_uint(best);
        unsigned m    = __reduce_max_sync(0xffffffffu, bb);
        unsigned cand = (bb == m) ? (unsigned)tid : 0xffffffffu;
        unsigned mi   = __reduce_min_sync(0xffffffffu, cand);
        if (lane == 0) s_key[warp] = ((ull)m << 32) | (ull)mi;
        __syncthreads();

        // stage 2: all warps redundantly reduce over 16 warp keys (+16 neutral)
        ull k = s_key[lane];
        unsigned wb = (unsigned)(k >> 32), wi = (unsigned)k;
        unsigned m2 = __reduce_max_sync(0xffffffffu, wb);
        unsigned c2 = (wb == m2) ? wi : 0xffffffffu;
        unsigned t2 = __reduce_min_sync(0xffffffffu, c2);

        if ((unsigned)tid == t2) {
            // first j (ascending) with dist bits == m2
            int j = 0;
#pragma unroll
            for (int jj = 15; jj >= 0; jj--)
                if (__float_as_uint(dist[jj]) == m2) j = jj;
            int g = j >> 1;
            ull vx = cxp[0], vy = cyp[0], vz = czp[0];
#pragma unroll
            for (int gg = 1; gg < 8; gg++) {
                vx = (g == gg) ? cxp[gg] : vx;
                vy = (g == gg) ? cyp[gg] : vy;
                vz = (g == gg) ? czp[gg] : vz;
            }
            float xl, xh, yl, yh, zl, zh;
            unpack2(vx, xl, xh); unpack2(vy, yl, yh); unpack2(vz, zl, zh);
            float X0 = (j & 1) ? xh : xl;
            float Y0 = (j & 1) ? yh : yl;
            float Z0 = (j & 1) ? zh : zl;
            s_cp[0] = pack2(-X0, -X0);
            s_cp[1] = pack2(-Y0, -Y0);
            s_cp[2] = pack2(-Z0, -Z0);
            float* o = out + ((size_t)b * SS + s) * 3;
            o[0] = X0; o[1] = Y0; o[2] = Z0;
        }
        __syncthreads();
    }
}

// ------------------------ Ball query: one warp per query ---------------------
__global__ void __launch_bounds__(256)
k_ball(const float* __restrict__ xyz, const float* __restrict__ newxyz) {
    const float R2 = (float)(0.2 * 0.2);
    int warp = threadIdx.x >> 5, lane = threadIdx.x & 31;
    int q = blockIdx.x * 8 + warp;
    int b = q >> 10;
    const float* X = xyz + (size_t)b * NN * 3;
    float nx = newxyz[q * 3], ny = newxyz[q * 3 + 1], nz = newxyz[q * 3 + 2];
    float s2 = __fadd_rn(__fadd_rn(__fmul_rn(nx, nx), __fmul_rn(ny, ny)),
                         __fmul_rn(nz, nz));
    __shared__ int s_list[8][KK];
    int found = 0;
    for (int basep = 0; basep < NN; basep += 32) {
        int n = basep + lane;
        float x = X[n * 3], y = X[n * 3 + 1], z = X[n * 3 + 2];
        float n2  = __fadd_rn(__fadd_rn(__fmul_rn(x, x), __fmul_rn(y, y)),
                              __fmul_rn(z, z));
        float dot = __fadd_rn(__fadd_rn(__fmul_rn(nx, x), __fmul_rn(ny, y)),
                              __fmul_rn(nz, z));
        float sq  = __fsub_rn(__fadd_rn(s2, n2), __fmul_rn(2.0f, dot));
        bool pass = !(sq > R2);
        unsigned msk = __ballot_sync(0xffffffffu, pass);
        int pos = found + __popc(msk & ((1u << lane) - 1u));
        if (pass && pos < KK) s_list[warp][pos] = n;
        found += __popc(msk);
        if (found >= KK) break;
    }
    __syncwarp();
    int cnt = found < KK ? found : KK;
    int first = s_list[warp][0];
    int v = (lane < cnt) ? s_list[warp][lane] : first;
    g_gidx[q * KK + lane] = v;
}

// ---------------- Layer0: gather + 9->64 matmul (f32x2) + stats --------------
__global__ void __launch_bounds__(256)
k_layer0(const float* __restrict__ points, const float* __restrict__ xyz,
         const float* __restrict__ newxyz, const float* __restrict__ W0,
         const float* __restrict__ b0) {
    __shared__ __align__(16) float s_W[9 * 64];
    __shared__ __align__(16) float s_b[64];
    __shared__ __align__(16) int   s_idx[128];
    __shared__ __align__(16) ull   s_f2[2][16][9];
    __shared__ float s_red[16][64];
    int tid = threadIdx.x;
    int row0 = blockIdx.x * 128;
    for (int i = tid; i < 576; i += 256) s_W[i] = W0[i];
    if (tid < 64) s_b[tid] = b0[tid];
    if (tid < 32) *reinterpret_cast<int4*>(&s_idx[tid * 4]) =
        *reinterpret_cast<const int4*>(&g_gidx[row0 + tid * 4]);
    __syncthreads();

    int r = tid >> 4, cg = tid & 15, c0 = cg * 4;
    ulonglong2 bp = *reinterpret_cast<const ulonglong2*>(&s_b[c0]);
    ull ls01 = 0, ls23 = 0, lq01 = 0, lq23 = 0;

    const bool ld = tid < 144;
    int lrr = tid / 9, lj = tid - lrr * 9;
    const int bidx = row0 >> 15;

    auto load_feat = [&](int t) -> float {
        int row = row0 + t * 16 + lrr;
        int i = s_idx[t * 16 + lrr];
        if (lj < 6) {
            return points[((size_t)bidx * NN + i) * 6 + lj];
        } else {
            int q = row >> 5, cc = lj - 6;
            return xyz[((size_t)bidx * NN + i) * 3 + cc] - newxyz[(size_t)q * 3 + cc];
        }
    };

    float fcur = 0.f;
    if (ld) fcur = load_feat(0);

    for (int t = 0; t < 8; t++) {
        if (ld) s_f2[t & 1][lrr][lj] = pack2(fcur, fcur);
        __syncthreads();
        if (ld && t < 7) fcur = load_feat(t + 1);

        ull a01 = bp.x, a23 = bp.y;
#pragma unroll
        for (int j = 0; j < 9; j++) {
            ull f = s_f2[t & 1][r][j];
            ulonglong2 w = *reinterpret_cast<const ulonglong2*>(&s_W[j * 64 + c0]);
            a01 = fma2(f, w.x, a01);
            a23 = fma2(f, w.y, a23);
        }
        ulonglong2 o; o.x = a01; o.y = a23;
        *reinterpret_cast<ulonglong2*>(&g_h0[(size_t)(row0 + t * 16 + r) * 64 + c0]) = o;
        ls01 = add2(ls01, a01); ls23 = add2(ls23, a23);
        lq01 = fma2(a01, a01, lq01); lq23 = fma2(a23, a23, lq23);
    }
    float l0, l1, l2, l3;
    unpack2(ls01, l0, l1); unpack2(ls23, l2, l3);
    s_red[r][c0] = l0; s_red[r][c0+1] = l1; s_red[r][c0+2] = l2; s_red[r][c0+3] = l3;
    __syncthreads();
    if (tid < 64) {
        float t0 = 0.f;
#pragma unroll
        for (int rr = 0; rr < 16; rr++) t0 += s_red[rr][tid];
        atomicAdd(&g_sum[tid], (double)t0);
    }
    __syncthreads();
    unpack2(lq01, l0, l1); unpack2(lq23, l2, l3);
    s_red[r][c0] = l0; s_red[r][c0+1] = l1; s_red[r][c0+2] = l2; s_red[r][c0+3] = l3;
    __syncthreads();
    if (tid < 64) {
        float t0 = 0.f;
#pragma unroll
        for (int rr = 0; rr < 16; rr++) t0 += s_red[rr][tid];
        atomicAdd(&g_sq[tid], (double)t0);
    }
}

// -------------------------------- BN finalize --------------------------------
__global__ void k_finalize(const float* __restrict__ g, const float* __restrict__ be,
                           int off, int C) {
    int c = threadIdx.x;
    if (c < C) {
        const double invM = 1.0 / (double)M_ROWS;
        double m = g_sum[off + c] * invM;
        double v = g_sq[off + c] * invM - m * m;
        float rs = rsqrtf((float)v + EPSf);
        float a = g[c] * rs;
        g_a[off + c] = a;
        g_cs[off + c] = fmaf(-(float)m, a, be[c]);
    }
}

// -------------- Layer1: bn0+relu, 64->64 matmul (f32x2), stats ---------------
__global__ void __launch_bounds__(256)
k_layer1(const float* __restrict__ W1, const float* __restrict__ b1) {
    __shared__ __align__(16) float s_W[64 * 64];
    __shared__ __align__(16) float s_b[64];
    __shared__ float s_a[64], s_cs[64];
    __shared__ __align__(16) ull s_x2[32][64];
    __shared__ float s_red[16][64];
    int tid = threadIdx.x;
    for (int i = tid; i < 4096; i += 256) s_W[i] = W1[i];
    if (tid < 64) { s_b[tid] = b1[tid]; s_a[tid] = g_a[tid]; s_cs[tid] = g_cs[tid]; }
    __syncthreads();
    int rg = tid >> 4, cg = tid & 15, c0 = cg * 4;
    int r0 = rg * 2;
    ulonglong2 bp = *reinterpret_cast<const ulonglong2*>(&s_b[c0]);
    ull ls01 = 0, ls23 = 0, lq01 = 0, lq23 = 0;

    for (int t = 0; t < 4; t++) {
        int row0 = (blockIdx.x * 4 + t) * 32;
#pragma unroll
        for (int e = 0; e < 4; e++) {
            int lin = e * 256 + tid;
            int rr = lin >> 5, jj = (lin & 31) * 2;
            float2 v = *reinterpret_cast<const float2*>(&g_h0[(size_t)(row0 + rr) * 64 + jj]);
            float v0 = fmaxf(fmaf(v.x, s_a[jj],     s_cs[jj]),     0.f);
            float v1 = fmaxf(fmaf(v.y, s_a[jj + 1], s_cs[jj + 1]), 0.f);
            ulonglong2 st; st.x = pack2(v0, v0); st.y = pack2(v1, v1);
            *reinterpret_cast<ulonglong2*>(&s_x2[rr][jj]) = st;
        }
        __syncthreads();
        ull a01_0 = bp.x, a23_0 = bp.y, a01_1 = bp.x, a23_1 = bp.y;
#pragma unroll
        for (int j = 0; j < 64; j++) {
            ull x0 = s_x2[r0][j], x1 = s_x2[r0 + 1][j];
            ulonglong2 w = *reinterpret_cast<const ulonglong2*>(&s_W[j * 64 + c0]);
            a01_0 = fma2(x0, w.x, a01_0); a23_0 = fma2(x0, w.y, a23_0);
            a01_1 = fma2(x1, w.x, a01_1); a23_1 = fma2(x1, w.y, a23_1);
        }
        ulonglong2 o;
        o.x = a01_0; o.y = a23_0;
        *reinterpret_cast<ulonglong2*>(&g_h1[(size_t)(row0 + r0) * 64 + c0]) = o;
        o.x = a01_1; o.y = a23_1;
        *reinterpret_cast<ulonglong2*>(&g_h1[(size_t)(row0 + r0 + 1) * 64 + c0]) = o;
        ls01 = add2(add2(ls01, a01_0), a01_1);
        ls23 = add2(add2(ls23, a23_0), a23_1);
        lq01 = fma2(a01_0, a01_0, lq01); lq01 = fma2(a01_1, a01_1, lq01);
        lq23 = fma2(a23_0, a23_0, lq23); lq23 = fma2(a23_1, a23_1, lq23);
        __syncthreads();
    }
    float l0, l1, l2, l3;
    unpack2(ls01, l0, l1); unpack2(ls23, l2, l3);
    s_red[rg][c0] = l0; s_red[rg][c0+1] = l1; s_red[rg][c0+2] = l2; s_red[rg][c0+3] = l3;
    __syncthreads();
    if (tid < 64) {
        float t0 = 0.f;
#pragma unroll
        for (int rr = 0; rr < 16; rr++) t0 += s_red[rr][tid];
        atomicAdd(&g_sum[64 + tid], (double)t0);
    }
    __syncthreads();
    unpack2(lq01, l0, l1); unpack2(lq23, l2, l3);
    s_red[rg][c0] = l0; s_red[rg][c0+1] = l1; s_red[rg][c0+2] = l2; s_red[rg][c0+3] = l3;
    __syncthreads();
    if (tid < 64) {
        float t0 = 0.f;
#pragma unroll
        for (int rr = 0; rr < 16; rr++) t0 += s_red[rr][tid];
        atomicAdd(&g_sq[64 + tid], (double)t0);
    }
}

// ------ Layer2: bn1+relu, 64->128 matmul (f32x2), stats, fused max/min ------
__global__ void __launch_bounds__(256)
k_layer2(const float* __restrict__ W2, const float* __restrict__ b2) {
    __shared__ __align__(16) float s_W[64 * 128];
    __shared__ __align__(16) float s_b[128];
    __shared__ float s_a[64], s_cs[64];
    __shared__ __align__(16) ull s_x2[16][64];
    __shared__ float s_red[8][128];
    int tid = threadIdx.x;
    for (int i = tid; i < 8192; i += 256) s_W[i] = W2[i];
    if (tid < 128) s_b[tid] = b2[tid];
    if (tid < 64) { s_a[tid] = g_a[64 + tid]; s_cs[tid] = g_cs[64 + tid]; }
    __syncthreads();
    int rg = tid >> 5, cg = tid & 31, c0 = cg * 4;
    int r0 = rg * 2;
    ulonglong2 bp = *reinterpret_cast<const ulonglong2*>(&s_b[c0]);
    ull ls01 = 0, ls23 = 0, lq01 = 0, lq23 = 0;
    float mx0 = -3.402823466e38f, mx1 = mx0, mx2 = mx0, mx3 = mx0;
    float mn0 =  3.402823466e38f, mn1 = mn0, mn2 = mn0, mn3 = mn0;

    for (int t = 0; t < 8; t++) {
        int row0 = (blockIdx.x * 8 + t) * 16;
#pragma unroll
        for (int e = 0; e < 2; e++) {
            int lin = e * 256 + tid;
            int rr = lin >> 5, jj = (lin & 31) * 2;
            float2 v = *reinterpret_cast<const float2*>(&g_h1[(size_t)(row0 + rr) * 64 + jj]);
            float v0 = fmaxf(fmaf(v.x, s_a[jj],     s_cs[jj]),     0.f);
            float v1 = fmaxf(fmaf(v.y, s_a[jj + 1], s_cs[jj + 1]), 0.f);
            ulonglong2 st; st.x = pack2(v0, v0); st.y = pack2(v1, v1);
            *reinterpret_cast<ulonglong2*>(&s_x2[rr][jj]) = st;
        }
        __syncthreads();
        ull a01_0 = bp.x, a23_0 = bp.y, a01_1 = bp.x, a23_1 = bp.y;
#pragma unroll
        for (int j = 0; j < 64; j++) {
            ull x0 = s_x2[r0][j], x1 = s_x2[r0 + 1][j];
            ulonglong2 w = *reinterpret_cast<const ulonglong2*>(&s_W[j * 128 + c0]);
            a01_0 = fma2(x0, w.x, a01_0); a23_0 = fma2(x0, w.y, a23_0);
            a01_1 = fma2(x1, w.x, a01_1); a23_1 = fma2(x1, w.y, a23_1);
        }
        ls01 = add2(add2(ls01, a01_0), a01_1);
        ls23 = add2(add2(ls23, a23_0), a23_1);
        lq01 = fma2(a01_0, a01_0, lq01); lq01 = fma2(a01_1, a01_1, lq01);
        lq23 = fma2(a23_0, a23_0, lq23); lq23 = fma2(a23_1, a23_1, lq23);

        float e0, e1, e2, e3, f0, f1, f2, f3;
        unpack2(a01_0, e0, e1); unpack2(a23_0, e2, e3);
        unpack2(a01_1, f0, f1); unpack2(a23_1, f2, f3);
        mx0 = fmaxf(mx0, fmaxf(e0, f0)); mn0 = fminf(mn0, fminf(e0, f0));
        mx1 = fmaxf(mx1, fmaxf(e1, f1)); mn1 = fminf(mn1, fminf(e1, f1));
        mx2 = fmaxf(mx2, fmaxf(e2, f2)); mn2 = fminf(mn2, fminf(e2, f2));
        mx3 = fmaxf(mx3, fmaxf(e3, f3)); mn3 = fminf(mn3, fminf(e3, f3));

        if (t & 1) {
            int q = blockIdx.x * 4 + (t >> 1);
            s_red[rg][c0] = mx0; s_red[rg][c0+1] = mx1; s_red[rg][c0+2] = mx2; s_red[rg][c0+3] = mx3;
            __syncthreads();
            if (tid < 128) {
                float m = s_red[0][tid];
#pragma unroll
                for (int rr = 1; rr < 8; rr++) m = fmaxf(m, s_red[rr][tid]);
                g_mx[(size_t)q * 128 + tid] = m;
            }
            __syncthreads();
            s_red[rg][c0] = mn0; s_red[rg][c0+1] = mn1; s_red[rg][c0+2] = mn2; s_red[rg][c0+3] = mn3;
            __syncthreads();
            if (tid < 128) {
                float m = s_red[0][tid];
#pragma unroll
                for (int rr = 1; rr < 8; rr++) m = fminf(m, s_red[rr][tid]);
                g_mn[(size_t)q * 128 + tid] = m;
            }
            mx0 = mx1 = mx2 = mx3 = -3.402823466e38f;
            mn0 = mn1 = mn2 = mn3 =  3.402823466e38f;
        }
        __syncthreads();
    }
    float l0, l1, l2, l3;
    unpack2(ls01, l0, l1); unpack2(ls23, l2, l3);
    s_red[rg][c0] = l0; s_red[rg][c0+1] = l1; s_red[rg][c0+2] = l2; s_red[rg][c0+3] = l3;
    __syncthreads();
    if (tid < 128) {
        float t0 = 0.f;
#pragma unroll
        for (int rr = 0; rr < 8; rr++) t0 += s_red[rr][tid];
        atomicAdd(&g_sum[128 + tid], (double)t0);
    }
    __syncthreads();
    unpack2(lq01, l0, l1); unpack2(lq23, l2, l3);
    s_red[rg][c0] = l0; s_red[rg][c0+1] = l1; s_red[rg][c0+2] = l2; s_red[rg][c0+3] = l3;
    __syncthreads();
    if (tid < 128) {
        float t0 = 0.f;
#pragma unroll
        for (int rr = 0; rr < 8; rr++) t0 += s_red[rr][tid];
        atomicAdd(&g_sq[128 + tid], (double)t0);
    }
}

// --------- Final: BN2+relu applied to per-query max/min (exact fusion) -------
__global__ void __launch_bounds__(256)
k_out(float* __restrict__ out) {
    int i = blockIdx.x * 256 + threadIdx.x;
    int c = i & 127;
    float a = g_a[128 + c], cs = g_cs[128 + c];
    float v = (a >= 0.f) ? g_mx[i] : g_mn[i];
    out[(size_t)BB * SS * 3 + i] = fmaxf(fmaf(v, a, cs), 0.f);
}

// -----------------------------------------------------------------------------
extern "C" void kernel_launch(void* const* d_in, const int* in_sizes, int n_in,
                              void* d_out, int out_size) {
    const float* xyz    = (const float*)d_in[0];
    const float* points = (const float*)d_in[1];
    const float* W0 = (const float*)d_in[2];  const float* b0 = (const float*)d_in[3];
    const float* g0 = (const float*)d_in[4];  const float* be0 = (const float*)d_in[5];
    const float* W1 = (const float*)d_in[6];  const float* b1 = (const float*)d_in[7];
    const float* g1 = (const float*)d_in[8];  const float* be1 = (const float*)d_in[9];
    const float* W2 = (const float*)d_in[10]; const float* b2 = (const float*)d_in[11];
    const float* g2 = (const float*)d_in[12]; const float* be2 = (const float*)d_in[13];
    float* out = (float*)d_out;   // [B*S*3 new_xyz | B*S*128 new_points]

    k_init<<<1, 256>>>();
    k_fps<<<BB, 512>>>(xyz, out);
    k_ball<<<(BB * SS) / 8, 256>>>(xyz, out);
    k_layer0<<<2048, 256>>>(points, xyz, out, W0, b0);
    k_finalize<<<1, 64>>>(g0, be0, 0, 64);
    k_layer1<<<2048, 256>>>(W1, b1);
    k_finalize<<<1, 64>>>(g1, be1, 64, 64);
    k_layer2<<<2048, 256>>>(W2, b2);
    k_finalize<<<1, 128>>>(g2, be2, 128, 128);
    k_out<<<(BB * SS * 128) / 256, 256>>>(out);
}